// round 3
// baseline (speedup 1.0000x reference)
#include <cuda_runtime.h>
#include <math.h>

#define BATCH 2
#define NC 8
#define NE 16
#define NSEG 17
#define DD 64
#define HH 128
#define WW 128
#define NVOX (DD*HH*WW)      /* 1048576 per batch */
#define NTOT (BATCH*NVOX)

// ---------------- scratch (device globals; no allocation) ----------------
__device__ int   g_packed[NTOT];       // label | (boundary ? sign bit : 0)
__device__ float g_nll;
__device__ float g_cardp[BATCH][NC];
__device__ float g_inter[BATCH][NC];
__device__ float g_hist[BATCH][NC];    // class counts (= cardg)
__device__ float g_cnt[BATCH][NSEG];
__device__ float g_bcnt[BATCH][NSEG];  // boundary counts per segment
__device__ float g_cnum[BATCH][NSEG][NE];
__device__ float g_centers[BATCH][NSEG][NE];
__device__ float g_pull[BATCH][NSEG];
__device__ float g_push[BATCH];
__device__ float g_normv[BATCH];
__device__ float g_val[BATCH];

// ---------------- zero accumulators ----------------
__global__ void zero_kernel() {
    int t = blockIdx.x * blockDim.x + threadIdx.x;
    if (t < BATCH*NC) {
        (&g_cardp[0][0])[t] = 0.f;
        (&g_inter[0][0])[t] = 0.f;
        (&g_hist[0][0])[t]  = 0.f;
    }
    if (t < BATCH*NSEG) {
        (&g_cnt[0][0])[t]  = 0.f;
        (&g_bcnt[0][0])[t] = 0.f;
        (&g_pull[0][0])[t] = 0.f;
    }
    if (t < BATCH*NSEG*NE) (&g_cnum[0][0][0])[t] = 0.f;
    if (t < BATCH) { g_push[t] = 0.f; g_normv[t] = 0.f; g_val[t] = 0.f; }
    if (t == 0) g_nll = 0.f;
}

// ------ prep: boundary + pack + segment/class histograms ------
__global__ void __launch_bounds__(256) prep_kernel(const int* __restrict__ lab,
                                                   const int* __restrict__ cls) {
    __shared__ float s_cnt[NSEG], s_bcnt[NSEG], s_hist[NC];
    if (threadIdx.x < NSEG) { s_cnt[threadIdx.x] = 0.f; s_bcnt[threadIdx.x] = 0.f; }
    if (threadIdx.x < NC) s_hist[threadIdx.x] = 0.f;
    __syncthreads();

    int idx = blockIdx.x * blockDim.x + threadIdx.x;
    int b = idx >> 20;
    int v = idx & (NVOX - 1);
    int d = v >> 14;
    int r = v & 16383;
    int h = r >> 7;
    int x = r & 127;
    const int* Lb = lab + (size_t)b * NVOX;
    int c0 = Lb[v];
    bool diff = false;
#pragma unroll
    for (int dd = -1; dd <= 1; dd++) {
        int zd = min(max(d + dd, 0), DD - 1);
#pragma unroll
        for (int dh = -1; dh <= 1; dh++) {
            int zh = min(max(h + dh, 0), HH - 1);
#pragma unroll
            for (int dx = -1; dx <= 1; dx++) {
                int zx = min(max(x + dx, 0), WW - 1);
                diff |= (Lb[(zd << 14) + (zh << 7) + zx] != c0);
            }
        }
    }
    g_packed[idx] = c0 | (diff ? 0x80000000 : 0);

    atomicAdd(&s_cnt[c0], 1.f);
    if (diff) atomicAdd(&s_bcnt[c0], 1.f);
    int cl = cls[idx];
    atomicAdd(&s_hist[cl], 1.f);

    __syncthreads();
    if (threadIdx.x < NSEG) {
        if (s_cnt[threadIdx.x]  != 0.f) atomicAdd(&g_cnt[b][threadIdx.x],  s_cnt[threadIdx.x]);
        if (s_bcnt[threadIdx.x] != 0.f) atomicAdd(&g_bcnt[b][threadIdx.x], s_bcnt[threadIdx.x]);
    }
    if (threadIdx.x < NC && s_hist[threadIdx.x] != 0.f)
        atomicAdd(&g_hist[b][threadIdx.x], s_hist[threadIdx.x]);
}

// ---------------- CE + Dice fused pass over sem_logits (scalar/voxel) -------
__global__ void __launch_bounds__(256, 7) ce_dice_kernel(const float* __restrict__ logits,
                                                         const int* __restrict__ cls) {
    int b = blockIdx.y;
    const float* lb = logits + (size_t)b * NC * NVOX;
    const int*   cb = cls + (size_t)b * NVOX;

    float r_nll = 0.f;
    float r_cardp[NC], r_inter[NC];
#pragma unroll
    for (int c = 0; c < NC; c++) { r_cardp[c]=0.f; r_inter[c]=0.f; }

    int stride = gridDim.x * blockDim.x;
    for (int i = blockIdx.x * blockDim.x + threadIdx.x; i < NVOX; i += stride) {
        float xv[NC];
#pragma unroll
        for (int c = 0; c < NC; c++) xv[c] = lb[(size_t)c * NVOX + i];
        int t = cb[i];

        float m = xv[0];
#pragma unroll
        for (int c = 1; c < NC; c++) m = fmaxf(m, xv[c]);
        float ex[NC]; float s = 0.f;
#pragma unroll
        for (int c = 0; c < NC; c++) { ex[c] = __expf(xv[c] - m); s += ex[c]; }
        float inv = 1.0f / s;
        float lse = m + __logf(s);
#pragma unroll
        for (int c = 0; c < NC; c++) {
            float p = ex[c] * inv;
            r_cardp[c] += p;
            if (t == c) {
                r_inter[c] += p;
                r_nll += lse - xv[c];
            }
        }
    }

    __shared__ float s_acc[17];
    if (threadIdx.x < 17) s_acc[threadIdx.x] = 0.f;
    __syncthreads();
    float vals[17];
    vals[0] = r_nll;
#pragma unroll
    for (int c = 0; c < NC; c++) { vals[1+c]=r_cardp[c]; vals[9+c]=r_inter[c]; }
#pragma unroll
    for (int k = 0; k < 17; k++) {
        float v = vals[k];
#pragma unroll
        for (int o = 16; o; o >>= 1) v += __shfl_xor_sync(0xffffffffu, v, o);
        if ((threadIdx.x & 31) == 0) atomicAdd(&s_acc[k], v);
    }
    __syncthreads();
    int t = threadIdx.x;
    if (t == 0)       atomicAdd(&g_nll, s_acc[0]);
    else if (t < 9)   atomicAdd(&g_cardp[b][t-1], s_acc[t]);
    else if (t < 17)  atomicAdd(&g_inter[b][t-9], s_acc[t]);
}

// ------- pass A: weighted segment sums (2 channels/group, lane-rotated) -----
#define SEG_CH 2
__global__ void __launch_bounds__(256, 8) segstat_kernel(const float* __restrict__ embed) {
    int b = blockIdx.y;
    int g = blockIdx.z;                 // channels [2g, 2g+2)
    __shared__ float s_cnum[NSEG][3];   // stride 3: conflict-free banks
    for (int j = threadIdx.x; j < NSEG*3; j += blockDim.x) (&s_cnum[0][0])[j] = 0.f;
    __syncthreads();

    const float4* eb = (const float4*)(embed + ((size_t)b * NE + g * SEG_CH) * NVOX);
    const int4*   pb = (const int4*)(g_packed + (size_t)b * NVOX);
    int lane1 = threadIdx.x & 1;

    int stride = gridDim.x * blockDim.x;
    for (int i = blockIdx.x * blockDim.x + threadIdx.x; i < NVOX/4; i += stride) {
        float4 ea = eb[i];
        float4 ec = eb[NVOX/4 + i];
        int4 p4 = pb[i];
#pragma unroll
        for (int j = 0; j < 4; j++) {
            int p = (j==0) ? p4.x : (j==1) ? p4.y : (j==2) ? p4.z : p4.w;
            int l = p & 0x7fffffff;
            float wv = (p < 0) ? 10.f : 1.f;
            float va = ((j==0) ? ea.x : (j==1) ? ea.y : (j==2) ? ea.z : ea.w) * wv;
            float vb = ((j==0) ? ec.x : (j==1) ? ec.y : (j==2) ? ec.z : ec.w) * wv;
#pragma unroll
            for (int s = 0; s < 2; s++) {
                int c = lane1 ^ s;
                float v = c ? vb : va;
                atomicAdd(&s_cnum[l][c], v);
            }
        }
    }
    __syncthreads();
    for (int j = threadIdx.x; j < NSEG*SEG_CH; j += blockDim.x) {
        int k = j >> 1, c = j & 1;
        atomicAdd(&g_cnum[b][k][g*SEG_CH + c], s_cnum[k][c]);
    }
}

// ---------------- centers + push + norm (tiny) ----------------
__global__ void centers_kernel() {
    int b = blockIdx.x;
    __shared__ float sc[NSEG][NE + 1];
    __shared__ int   s_present[NSEG];
    __shared__ float s_push, s_norm;
    __shared__ int   s_np;
    int tid = threadIdx.x;
    if (tid == 0) { s_push = 0.f; s_norm = 0.f; s_np = 0; }
    for (int j = tid; j < NSEG*NE; j += blockDim.x) {
        int k = j / NE, c = j % NE;
        float wsum = g_cnt[b][k] + 9.0f * g_bcnt[b][k];
        float cen = g_cnum[b][k][c] / (wsum + 1e-8f);
        g_centers[b][k][c] = cen;
        sc[k][c] = cen;
    }
    for (int k = tid; k < NSEG; k += blockDim.x) s_present[k] = (g_cnt[b][k] > 0.f) ? 1 : 0;
    __syncthreads();
    if (tid == 0) {
        int np = 0;
        for (int k = 1; k < NSEG; k++) np += s_present[k];
        s_np = np;
    }
    float pacc = 0.f;
    for (int p = tid; p < 120; p += blockDim.x) {
        int i = 1, rem = p;
        while (rem >= (NSEG - 1) - i) { rem -= (NSEG - 1) - i; i++; }
        int jj = i + 1 + rem;
        float ds = 0.f;
#pragma unroll
        for (int c = 0; c < NE; c++) { float dv = sc[i][c] - sc[jj][c]; ds += dv * dv; }
        float pw = sqrtf(ds);
        float tt = fmaxf(3.0f - pw, 0.f);
        if (s_present[i] && s_present[jj]) pacc += tt * tt;
    }
    atomicAdd(&s_push, pacc);
    float nacc = 0.f;
    for (int k = 1 + tid; k < NSEG; k += blockDim.x) {
        if (s_present[k]) {
            float ds = 0.f;
#pragma unroll
            for (int c = 0; c < NE; c++) ds += sc[k][c] * sc[k][c];
            nacc += sqrtf(ds);
        }
    }
    atomicAdd(&s_norm, nacc);
    __syncthreads();
    if (tid == 0) {
        float np = (float)s_np;
        float npairs = np * (np - 1.f) * 0.5f;
        g_push[b]  = (npairs > 0.f) ? s_push / fmaxf(npairs, 1.f) : 0.f;
        g_normv[b] = (np > 0.f)     ? s_norm / fmaxf(np, 1.f)     : 0.f;
        g_val[b]   = (np > 0.f) ? 1.f : 0.f;
    }
}

// ---------------- pass B: pull (scalar per voxel) ----------------
__global__ void __launch_bounds__(256, 8) pull_kernel(const float* __restrict__ embed) {
    int b = blockIdx.y;
    __shared__ float sc[NSEG][NE + 1];
    __shared__ float s_pull[NSEG];
    for (int j = threadIdx.x; j < NSEG*NE; j += blockDim.x)
        sc[j / NE][j % NE] = g_centers[b][j / NE][j % NE];
    for (int j = threadIdx.x; j < NSEG; j += blockDim.x) s_pull[j] = 0.f;
    __syncthreads();

    const float* eb = embed + (size_t)b * NE * NVOX;
    const int*   pb = g_packed + (size_t)b * NVOX;

    int stride = gridDim.x * blockDim.x;
    for (int i = blockIdx.x * blockDim.x + threadIdx.x; i < NVOX; i += stride) {
        int p = pb[i];
        int l = p & 0x7fffffff;
        float wv = (p < 0) ? 10.f : 1.f;
        float ev[NE];
#pragma unroll
        for (int c = 0; c < NE; c++) ev[c] = eb[(size_t)c * NVOX + i];
        float ds = 0.f;
#pragma unroll
        for (int c = 0; c < NE; c++) {
            float dv = ev[c] - sc[l][c];
            ds += dv * dv;
        }
        float dist = sqrtf(ds);
        float tt = fmaxf(dist - 0.5f, 0.f);
        atomicAdd(&s_pull[l], tt * tt * wv);
    }
    __syncthreads();
    for (int j = threadIdx.x; j < NSEG; j += blockDim.x)
        atomicAdd(&g_pull[b][j], s_pull[j]);
}

// ---------------- final combine ----------------
__global__ void final_kernel(float* __restrict__ out) {
    if (threadIdx.x != 0 || blockIdx.x != 0) return;
    float Nf = (float)NTOT;
    float ce = g_nll / Nf;

    float dsum = 0.f;
    for (int b = 0; b < BATCH; b++)
        for (int c = 0; c < NC; c++)
            dsum += (2.0f * g_inter[b][c] + 1e-5f) /
                    (g_cardp[b][c] + g_hist[b][c] + 1e-5f);
    float dice = 1.0f - dsum / (float)(BATCH * NC);

    float lp = 0.f;
    for (int b = 0; b < BATCH; b++)
        for (int k = 1; k < NSEG; k++)
            if (g_cnt[b][k] > 0.f)
                lp += g_pull[b][k] / fmaxf(g_cnt[b][k], 1.f);

    float push = 0.f, nrm = 0.f, val = 0.f;
    for (int b = 0; b < BATCH; b++) { push += g_push[b]; nrm += g_normv[b]; val += g_val[b]; }

    float ins = (1.0f * lp + 1.0f * push + 0.001f * nrm) / fmaxf(val, 1.f);
    float sem = ce + dice;
    out[0] = sem + ins;
    out[1] = sem;
    out[2] = ce;
    out[3] = dice;
    out[4] = ins;
}

// ---------------- launch ----------------
extern "C" void kernel_launch(void* const* d_in, const int* in_sizes, int n_in,
                              void* d_out, int out_size) {
    const float* sem = (const float*)d_in[0];
    const float* emb = (const float*)d_in[1];
    const int*   cls = (const int*)d_in[2];
    const int*   lab = (const int*)d_in[3];
    float* out = (float*)d_out;

    zero_kernel<<<3, 256>>>();

    prep_kernel<<<NTOT / 256, 256>>>(lab, cls);

    dim3 g1(296, BATCH);
    ce_dice_kernel<<<g1, 256>>>(sem, cls);

    dim3 g2(148, BATCH, NE / SEG_CH);
    segstat_kernel<<<g2, 256>>>(emb);

    centers_kernel<<<BATCH, 128>>>();

    dim3 g3(296, BATCH);
    pull_kernel<<<g3, 256>>>(emb);

    final_kernel<<<1, 32>>>(out);
}

// round 4
// speedup vs baseline: 1.2614x; 1.2614x over previous
#include <cuda_runtime.h>
#include <math.h>

#define BATCH 2
#define NC 8
#define NE 16
#define NSEG 17
#define DD 64
#define HH 128
#define WW 128
#define NVOX (DD*HH*WW)      /* 1048576 per batch */
#define NTOT (BATCH*NVOX)

// ---------------- scratch (device globals; no allocation) ----------------
__device__ int   g_packed[NTOT];       // label | (boundary ? sign bit : 0)
__device__ float g_nll;
__device__ float g_cardp[BATCH][NC];
__device__ float g_inter[BATCH][NC];
__device__ float g_hist[BATCH][NC];    // class counts (= cardg)
__device__ float g_cnt[BATCH][NSEG];
__device__ float g_bcnt[BATCH][NSEG];  // boundary counts per segment
__device__ float g_cnum[BATCH][NSEG][NE];
__device__ float g_centers[BATCH][NSEG][NE];
__device__ float g_pull[BATCH][NSEG];
__device__ float g_push[BATCH];
__device__ float g_normv[BATCH];
__device__ float g_val[BATCH];

// one setp, two predicated packed-f32x2 adds (4 channels per segment test)
#define PRED_ADD2x2(a01, a23, lv, kv, v01, v23)                          \
    asm volatile("{\n\t"                                                 \
                 ".reg .pred p;\n\t"                                     \
                 "setp.eq.s32 p, %2, %3;\n\t"                            \
                 "@p add.rn.f32x2 %0, %0, %4;\n\t"                       \
                 "@p add.rn.f32x2 %1, %1, %5;\n\t"                       \
                 "}"                                                     \
                 : "+l"(a01), "+l"(a23)                                  \
                 : "r"(lv), "r"(kv), "l"(v01), "l"(v23))

__device__ __forceinline__ unsigned long long pack2(float a, float b) {
    unsigned long long r;
    asm("mov.b64 %0, {%1, %2};" : "=l"(r) : "r"(__float_as_uint(a)), "r"(__float_as_uint(b)));
    return r;
}
__device__ __forceinline__ void unpack2(unsigned long long v, float& a, float& b) {
    unsigned lo, hi;
    asm("mov.b64 {%0, %1}, %2;" : "=r"(lo), "=r"(hi) : "l"(v));
    a = __uint_as_float(lo); b = __uint_as_float(hi);
}

// ---------------- zero accumulators ----------------
__global__ void zero_kernel() {
    int t = blockIdx.x * blockDim.x + threadIdx.x;
    if (t < BATCH*NC) {
        (&g_cardp[0][0])[t] = 0.f;
        (&g_inter[0][0])[t] = 0.f;
        (&g_hist[0][0])[t]  = 0.f;
    }
    if (t < BATCH*NSEG) {
        (&g_cnt[0][0])[t]  = 0.f;
        (&g_bcnt[0][0])[t] = 0.f;
        (&g_pull[0][0])[t] = 0.f;
    }
    if (t < BATCH*NSEG*NE) (&g_cnum[0][0][0])[t] = 0.f;
    if (t < BATCH) { g_push[t] = 0.f; g_normv[t] = 0.f; g_val[t] = 0.f; }
    if (t == 0) g_nll = 0.f;
}

// ------ prep: boundary + pack + segment/class histograms ------
__global__ void __launch_bounds__(256) prep_kernel(const int* __restrict__ lab,
                                                   const int* __restrict__ cls) {
    __shared__ float s_cnt[NSEG], s_bcnt[NSEG], s_hist[NC];
    if (threadIdx.x < NSEG) { s_cnt[threadIdx.x] = 0.f; s_bcnt[threadIdx.x] = 0.f; }
    if (threadIdx.x < NC) s_hist[threadIdx.x] = 0.f;
    __syncthreads();

    int idx = blockIdx.x * blockDim.x + threadIdx.x;
    int b = idx >> 20;
    int v = idx & (NVOX - 1);
    int d = v >> 14;
    int r = v & 16383;
    int h = r >> 7;
    int x = r & 127;
    const int* Lb = lab + (size_t)b * NVOX;
    int c0 = Lb[v];
    bool diff = false;
#pragma unroll
    for (int dd = -1; dd <= 1; dd++) {
        int zd = min(max(d + dd, 0), DD - 1);
#pragma unroll
        for (int dh = -1; dh <= 1; dh++) {
            int zh = min(max(h + dh, 0), HH - 1);
#pragma unroll
            for (int dx = -1; dx <= 1; dx++) {
                int zx = min(max(x + dx, 0), WW - 1);
                diff |= (Lb[(zd << 14) + (zh << 7) + zx] != c0);
            }
        }
    }
    g_packed[idx] = c0 | (diff ? 0x80000000 : 0);

    atomicAdd(&s_cnt[c0], 1.f);
    if (diff) atomicAdd(&s_bcnt[c0], 1.f);
    int cl = cls[idx];
    atomicAdd(&s_hist[cl], 1.f);

    __syncthreads();
    if (threadIdx.x < NSEG) {
        if (s_cnt[threadIdx.x]  != 0.f) atomicAdd(&g_cnt[b][threadIdx.x],  s_cnt[threadIdx.x]);
        if (s_bcnt[threadIdx.x] != 0.f) atomicAdd(&g_bcnt[b][threadIdx.x], s_bcnt[threadIdx.x]);
    }
    if (threadIdx.x < NC && s_hist[threadIdx.x] != 0.f)
        atomicAdd(&g_hist[b][threadIdx.x], s_hist[threadIdx.x]);
}

// ---------------- CE + Dice fused pass over sem_logits (vectorized) ---------
__global__ void __launch_bounds__(256) ce_dice_kernel(const float* __restrict__ logits,
                                                      const int* __restrict__ cls) {
    int b = blockIdx.y;
    const float4* lb = (const float4*)(logits + (size_t)b * NC * NVOX);
    const int4*   cb = (const int4*)(cls + (size_t)b * NVOX);

    float r_nll = 0.f;
    float r_cardp[NC], r_inter[NC];
#pragma unroll
    for (int c = 0; c < NC; c++) { r_cardp[c]=0.f; r_inter[c]=0.f; }

    int stride = gridDim.x * blockDim.x;
    for (int i = blockIdx.x * blockDim.x + threadIdx.x; i < NVOX/4; i += stride) {
        float4 x4[NC];
#pragma unroll
        for (int c = 0; c < NC; c++) x4[c] = lb[(size_t)c * (NVOX/4) + i];
        int4 t4 = cb[i];
#pragma unroll
        for (int j = 0; j < 4; j++) {
            float xv[NC];
#pragma unroll
            for (int c = 0; c < NC; c++)
                xv[c] = (j==0) ? x4[c].x : (j==1) ? x4[c].y : (j==2) ? x4[c].z : x4[c].w;
            int t = (j==0) ? t4.x : (j==1) ? t4.y : (j==2) ? t4.z : t4.w;

            float m = xv[0];
#pragma unroll
            for (int c = 1; c < NC; c++) m = fmaxf(m, xv[c]);
            float ex[NC]; float s = 0.f;
#pragma unroll
            for (int c = 0; c < NC; c++) { ex[c] = __expf(xv[c] - m); s += ex[c]; }
            float inv = 1.0f / s;
            float lse = m + __logf(s);
#pragma unroll
            for (int c = 0; c < NC; c++) {
                float p = ex[c] * inv;
                r_cardp[c] += p;
                if (t == c) {
                    r_inter[c] += p;
                    r_nll += lse - xv[c];
                }
            }
        }
    }

    __shared__ float s_acc[17];
    if (threadIdx.x < 17) s_acc[threadIdx.x] = 0.f;
    __syncthreads();
    float vals[17];
    vals[0] = r_nll;
#pragma unroll
    for (int c = 0; c < NC; c++) { vals[1+c]=r_cardp[c]; vals[9+c]=r_inter[c]; }
#pragma unroll
    for (int k = 0; k < 17; k++) {
        float v = vals[k];
#pragma unroll
        for (int o = 16; o; o >>= 1) v += __shfl_xor_sync(0xffffffffu, v, o);
        if ((threadIdx.x & 31) == 0) atomicAdd(&s_acc[k], v);
    }
    __syncthreads();
    int t = threadIdx.x;
    if (t == 0)       atomicAdd(&g_nll, s_acc[0]);
    else if (t < 9)   atomicAdd(&g_cardp[b][t-1], s_acc[t]);
    else if (t < 17)  atomicAdd(&g_inter[b][t-9], s_acc[t]);
}

// ------- pass A: predicated register accumulation (4 channels/group) --------
#define SEG_CH 4
__global__ void __launch_bounds__(256, 2) segstat_kernel(const float* __restrict__ embed) {
    int b = blockIdx.y;
    int g = blockIdx.z;                 // channels [4g, 4g+4)
    unsigned long long acc01[NSEG], acc23[NSEG];
#pragma unroll
    for (int k = 0; k < NSEG; k++) { acc01[k] = 0ull; acc23[k] = 0ull; }

    const float4* eb = (const float4*)(embed + ((size_t)b * NE + g * SEG_CH) * NVOX);
    const int4*   pb = (const int4*)(g_packed + (size_t)b * NVOX);

    int stride = gridDim.x * blockDim.x;
    for (int i = blockIdx.x * blockDim.x + threadIdx.x; i < NVOX/4; i += stride) {
        float4 e0 = eb[i];
        float4 e1 = eb[(size_t)(NVOX/4) + i];
        float4 e2 = eb[(size_t)2*(NVOX/4) + i];
        float4 e3 = eb[(size_t)3*(NVOX/4) + i];
        int4 p4 = pb[i];
#pragma unroll
        for (int j = 0; j < 4; j++) {
            int p = (j==0) ? p4.x : (j==1) ? p4.y : (j==2) ? p4.z : p4.w;
            int l = p & 0x7fffffff;
            float wv = (p < 0) ? 10.f : 1.f;
            float v0 = ((j==0) ? e0.x : (j==1) ? e0.y : (j==2) ? e0.z : e0.w) * wv;
            float v1 = ((j==0) ? e1.x : (j==1) ? e1.y : (j==2) ? e1.z : e1.w) * wv;
            float v2 = ((j==0) ? e2.x : (j==1) ? e2.y : (j==2) ? e2.z : e2.w) * wv;
            float v3 = ((j==0) ? e3.x : (j==1) ? e3.y : (j==2) ? e3.z : e3.w) * wv;
            unsigned long long v01 = pack2(v0, v1);
            unsigned long long v23 = pack2(v2, v3);
#pragma unroll
            for (int k = 0; k < NSEG; k++)
                PRED_ADD2x2(acc01[k], acc23[k], l, k, v01, v23);
        }
    }

    // reduce: warp shuffle on 64-bit packed pairs, then shared, then global
    __shared__ float s_cnum[NSEG][SEG_CH + 1];
    for (int j = threadIdx.x; j < NSEG*(SEG_CH+1); j += blockDim.x) (&s_cnum[0][0])[j] = 0.f;
    __syncthreads();
#pragma unroll
    for (int k = 0; k < NSEG; k++) {
        float a0, a1, a2, a3, b0, b1;
        unpack2(acc01[k], a0, a1);
        unpack2(acc23[k], a2, a3);
#pragma unroll
        for (int o = 16; o; o >>= 1) {
            a0 += __shfl_xor_sync(0xffffffffu, a0, o);
            a1 += __shfl_xor_sync(0xffffffffu, a1, o);
            a2 += __shfl_xor_sync(0xffffffffu, a2, o);
            a3 += __shfl_xor_sync(0xffffffffu, a3, o);
        }
        if ((threadIdx.x & 31) == 0) {
            atomicAdd(&s_cnum[k][0], a0);
            atomicAdd(&s_cnum[k][1], a1);
            atomicAdd(&s_cnum[k][2], a2);
            atomicAdd(&s_cnum[k][3], a3);
        }
        (void)b0; (void)b1;
    }
    __syncthreads();
    for (int j = threadIdx.x; j < NSEG*SEG_CH; j += blockDim.x) {
        int k = j >> 2, c = j & 3;
        atomicAdd(&g_cnum[b][k][g*SEG_CH + c], s_cnum[k][c]);
    }
}

// ---------------- centers + push + norm (tiny) ----------------
__global__ void centers_kernel() {
    int b = blockIdx.x;
    __shared__ float sc[NSEG][NE + 1];
    __shared__ int   s_present[NSEG];
    __shared__ float s_push, s_norm;
    __shared__ int   s_np;
    int tid = threadIdx.x;
    if (tid == 0) { s_push = 0.f; s_norm = 0.f; s_np = 0; }
    for (int j = tid; j < NSEG*NE; j += blockDim.x) {
        int k = j / NE, c = j % NE;
        float wsum = g_cnt[b][k] + 9.0f * g_bcnt[b][k];
        float cen = g_cnum[b][k][c] / (wsum + 1e-8f);
        g_centers[b][k][c] = cen;
        sc[k][c] = cen;
    }
    for (int k = tid; k < NSEG; k += blockDim.x) s_present[k] = (g_cnt[b][k] > 0.f) ? 1 : 0;
    __syncthreads();
    if (tid == 0) {
        int np = 0;
        for (int k = 1; k < NSEG; k++) np += s_present[k];
        s_np = np;
    }
    float pacc = 0.f;
    for (int p = tid; p < 120; p += blockDim.x) {
        int i = 1, rem = p;
        while (rem >= (NSEG - 1) - i) { rem -= (NSEG - 1) - i; i++; }
        int jj = i + 1 + rem;
        float ds = 0.f;
#pragma unroll
        for (int c = 0; c < NE; c++) { float dv = sc[i][c] - sc[jj][c]; ds += dv * dv; }
        float pw = sqrtf(ds);
        float tt = fmaxf(3.0f - pw, 0.f);
        if (s_present[i] && s_present[jj]) pacc += tt * tt;
    }
    atomicAdd(&s_push, pacc);
    float nacc = 0.f;
    for (int k = 1 + tid; k < NSEG; k += blockDim.x) {
        if (s_present[k]) {
            float ds = 0.f;
#pragma unroll
            for (int c = 0; c < NE; c++) ds += sc[k][c] * sc[k][c];
            nacc += sqrtf(ds);
        }
    }
    atomicAdd(&s_norm, nacc);
    __syncthreads();
    if (tid == 0) {
        float np = (float)s_np;
        float npairs = np * (np - 1.f) * 0.5f;
        g_push[b]  = (npairs > 0.f) ? s_push / fmaxf(npairs, 1.f) : 0.f;
        g_normv[b] = (np > 0.f)     ? s_norm / fmaxf(np, 1.f)     : 0.f;
        g_val[b]   = (np > 0.f) ? 1.f : 0.f;
    }
}

// ---------------- pass B: pull (vectorized, R2 form) ----------------
__global__ void __launch_bounds__(256, 3) pull_kernel(const float* __restrict__ embed) {
    int b = blockIdx.y;
    __shared__ float sc[NSEG][NE + 1];
    __shared__ float s_pull[NSEG];
    for (int j = threadIdx.x; j < NSEG*NE; j += blockDim.x)
        sc[j / NE][j % NE] = g_centers[b][j / NE][j % NE];
    for (int j = threadIdx.x; j < NSEG; j += blockDim.x) s_pull[j] = 0.f;
    __syncthreads();

    const float4* eb = (const float4*)(embed + (size_t)b * NE * NVOX);
    const int4*   pb = (const int4*)(g_packed + (size_t)b * NVOX);

    int stride = gridDim.x * blockDim.x;
    for (int i = blockIdx.x * blockDim.x + threadIdx.x; i < NVOX/4; i += stride) {
        int4 p4 = pb[i];
        int   lv[4]; float wv[4]; float ds[4];
#pragma unroll
        for (int j = 0; j < 4; j++) {
            int p = (j==0) ? p4.x : (j==1) ? p4.y : (j==2) ? p4.z : p4.w;
            lv[j] = p & 0x7fffffff;
            wv[j] = (p < 0) ? 10.f : 1.f;
            ds[j] = 0.f;
        }
#pragma unroll
        for (int half = 0; half < 2; half++) {
            float4 e4[8];
#pragma unroll
            for (int c = 0; c < 8; c++)
                e4[c] = eb[(size_t)(half*8 + c) * (NVOX/4) + i];
#pragma unroll
            for (int c = 0; c < 8; c++) {
                int cc = half*8 + c;
#pragma unroll
                for (int j = 0; j < 4; j++) {
                    float ev = (j==0) ? e4[c].x : (j==1) ? e4[c].y : (j==2) ? e4[c].z : e4[c].w;
                    float dv = ev - sc[lv[j]][cc];
                    ds[j] += dv * dv;
                }
            }
        }
#pragma unroll
        for (int j = 0; j < 4; j++) {
            float dist = sqrtf(ds[j]);
            float tt = fmaxf(dist - 0.5f, 0.f);
            atomicAdd(&s_pull[lv[j]], tt * tt * wv[j]);
        }
    }
    __syncthreads();
    for (int j = threadIdx.x; j < NSEG; j += blockDim.x)
        atomicAdd(&g_pull[b][j], s_pull[j]);
}

// ---------------- final combine ----------------
__global__ void final_kernel(float* __restrict__ out) {
    if (threadIdx.x != 0 || blockIdx.x != 0) return;
    float Nf = (float)NTOT;
    float ce = g_nll / Nf;

    float dsum = 0.f;
    for (int b = 0; b < BATCH; b++)
        for (int c = 0; c < NC; c++)
            dsum += (2.0f * g_inter[b][c] + 1e-5f) /
                    (g_cardp[b][c] + g_hist[b][c] + 1e-5f);
    float dice = 1.0f - dsum / (float)(BATCH * NC);

    float lp = 0.f;
    for (int b = 0; b < BATCH; b++)
        for (int k = 1; k < NSEG; k++)
            if (g_cnt[b][k] > 0.f)
                lp += g_pull[b][k] / fmaxf(g_cnt[b][k], 1.f);

    float push = 0.f, nrm = 0.f, val = 0.f;
    for (int b = 0; b < BATCH; b++) { push += g_push[b]; nrm += g_normv[b]; val += g_val[b]; }

    float ins = (1.0f * lp + 1.0f * push + 0.001f * nrm) / fmaxf(val, 1.f);
    float sem = ce + dice;
    out[0] = sem + ins;
    out[1] = sem;
    out[2] = ce;
    out[3] = dice;
    out[4] = ins;
}

// ---------------- launch ----------------
extern "C" void kernel_launch(void* const* d_in, const int* in_sizes, int n_in,
                              void* d_out, int out_size) {
    const float* sem = (const float*)d_in[0];
    const float* emb = (const float*)d_in[1];
    const int*   cls = (const int*)d_in[2];
    const int*   lab = (const int*)d_in[3];
    float* out = (float*)d_out;

    zero_kernel<<<3, 256>>>();

    prep_kernel<<<NTOT / 256, 256>>>(lab, cls);

    dim3 g1(296, BATCH);
    ce_dice_kernel<<<g1, 256>>>(sem, cls);

    dim3 g2(148, BATCH, NE / SEG_CH);
    segstat_kernel<<<g2, 256>>>(emb);

    centers_kernel<<<BATCH, 128>>>();

    dim3 g3(296, BATCH);
    pull_kernel<<<g3, 256>>>(emb);

    final_kernel<<<1, 32>>>(out);
}

// round 5
// speedup vs baseline: 1.5533x; 1.2314x over previous
#include <cuda_runtime.h>
#include <math.h>

#define BATCH 2
#define NC 8
#define NE 16
#define NSEG 17
#define DD 64
#define HH 128
#define WW 128
#define NVOX (DD*HH*WW)      /* 1048576 per batch */
#define NTOT (BATCH*NVOX)

// ---------------- scratch (device globals; no allocation) ----------------
__device__ int   g_packed[NTOT];       // label | (boundary ? sign bit : 0)
__device__ float g_nll;
__device__ float g_cardp[BATCH][NC];
__device__ float g_inter[BATCH][NC];
__device__ float g_hist[BATCH][NC];    // class counts (= cardg)
__device__ float g_cnt[BATCH][NSEG];
__device__ float g_bcnt[BATCH][NSEG];  // boundary counts per segment
__device__ float g_cnum[BATCH][NSEG][NE];
__device__ float g_centers[BATCH][NSEG][NE];
__device__ float g_pull[BATCH][NSEG];
__device__ float g_push[BATCH];
__device__ float g_normv[BATCH];
__device__ float g_val[BATCH];

// pack two f32 into bf16x2: low = x, high = y
__device__ __forceinline__ unsigned cvt_bf16x2(float x, float y) {
    unsigned d;
    asm("cvt.rn.bf16x2.f32 %0, %1, %2;" : "=r"(d) : "f"(y), "f"(x));
    return d;
}

// one-hot half: (label(p)==n) ? bf16(w(p)) : 0
__device__ __forceinline__ unsigned hb(int p, int n) {
    int l = p & 0x7fffffff;
    unsigned w = (p < 0) ? 0x4120u : 0x3F80u;   // bf16 10.0 : 1.0
    return (l == n) ? w : 0u;
}

// ---------------- zero accumulators ----------------
__global__ void zero_kernel() {
    int t = blockIdx.x * blockDim.x + threadIdx.x;
    if (t < BATCH*NC) {
        (&g_cardp[0][0])[t] = 0.f;
        (&g_inter[0][0])[t] = 0.f;
        (&g_hist[0][0])[t]  = 0.f;
    }
    if (t < BATCH*NSEG) {
        (&g_cnt[0][0])[t]  = 0.f;
        (&g_bcnt[0][0])[t] = 0.f;
        (&g_pull[0][0])[t] = 0.f;
    }
    if (t < BATCH*NSEG*NE) (&g_cnum[0][0][0])[t] = 0.f;
    if (t < BATCH) { g_push[t] = 0.f; g_normv[t] = 0.f; g_val[t] = 0.f; }
    if (t == 0) g_nll = 0.f;
}

// ------ prep: boundary + pack + segment/class histograms ------
__global__ void __launch_bounds__(256) prep_kernel(const int* __restrict__ lab,
                                                   const int* __restrict__ cls) {
    __shared__ float s_cnt[NSEG], s_bcnt[NSEG], s_hist[NC];
    if (threadIdx.x < NSEG) { s_cnt[threadIdx.x] = 0.f; s_bcnt[threadIdx.x] = 0.f; }
    if (threadIdx.x < NC) s_hist[threadIdx.x] = 0.f;
    __syncthreads();

    int idx = blockIdx.x * blockDim.x + threadIdx.x;
    int b = idx >> 20;
    int v = idx & (NVOX - 1);
    int d = v >> 14;
    int r = v & 16383;
    int h = r >> 7;
    int x = r & 127;
    const int* Lb = lab + (size_t)b * NVOX;
    int c0 = Lb[v];
    bool diff = false;
#pragma unroll
    for (int dd = -1; dd <= 1; dd++) {
        int zd = min(max(d + dd, 0), DD - 1);
#pragma unroll
        for (int dh = -1; dh <= 1; dh++) {
            int zh = min(max(h + dh, 0), HH - 1);
#pragma unroll
            for (int dx = -1; dx <= 1; dx++) {
                int zx = min(max(x + dx, 0), WW - 1);
                diff |= (Lb[(zd << 14) + (zh << 7) + zx] != c0);
            }
        }
    }
    g_packed[idx] = c0 | (diff ? 0x80000000 : 0);

    atomicAdd(&s_cnt[c0], 1.f);
    if (diff) atomicAdd(&s_bcnt[c0], 1.f);
    int cl = cls[idx];
    atomicAdd(&s_hist[cl], 1.f);

    __syncthreads();
    if (threadIdx.x < NSEG) {
        if (s_cnt[threadIdx.x]  != 0.f) atomicAdd(&g_cnt[b][threadIdx.x],  s_cnt[threadIdx.x]);
        if (s_bcnt[threadIdx.x] != 0.f) atomicAdd(&g_bcnt[b][threadIdx.x], s_bcnt[threadIdx.x]);
    }
    if (threadIdx.x < NC && s_hist[threadIdx.x] != 0.f)
        atomicAdd(&g_hist[b][threadIdx.x], s_hist[threadIdx.x]);
}

// ---------------- CE + Dice fused pass over sem_logits (vectorized) ---------
__global__ void __launch_bounds__(256) ce_dice_kernel(const float* __restrict__ logits,
                                                      const int* __restrict__ cls) {
    int b = blockIdx.y;
    const float4* lb = (const float4*)(logits + (size_t)b * NC * NVOX);
    const int4*   cb = (const int4*)(cls + (size_t)b * NVOX);

    float r_nll = 0.f;
    float r_cardp[NC], r_inter[NC];
#pragma unroll
    for (int c = 0; c < NC; c++) { r_cardp[c]=0.f; r_inter[c]=0.f; }

    int stride = gridDim.x * blockDim.x;
    for (int i = blockIdx.x * blockDim.x + threadIdx.x; i < NVOX/4; i += stride) {
        float4 x4[NC];
#pragma unroll
        for (int c = 0; c < NC; c++) x4[c] = lb[(size_t)c * (NVOX/4) + i];
        int4 t4 = cb[i];
#pragma unroll
        for (int j = 0; j < 4; j++) {
            float xv[NC];
#pragma unroll
            for (int c = 0; c < NC; c++)
                xv[c] = (j==0) ? x4[c].x : (j==1) ? x4[c].y : (j==2) ? x4[c].z : x4[c].w;
            int t = (j==0) ? t4.x : (j==1) ? t4.y : (j==2) ? t4.z : t4.w;

            float m = xv[0];
#pragma unroll
            for (int c = 1; c < NC; c++) m = fmaxf(m, xv[c]);
            float ex[NC]; float s = 0.f;
#pragma unroll
            for (int c = 0; c < NC; c++) { ex[c] = __expf(xv[c] - m); s += ex[c]; }
            float inv = 1.0f / s;
            float lse = m + __logf(s);
#pragma unroll
            for (int c = 0; c < NC; c++) {
                float p = ex[c] * inv;
                r_cardp[c] += p;
                if (t == c) {
                    r_inter[c] += p;
                    r_nll += lse - xv[c];
                }
            }
        }
    }

    __shared__ float s_acc[17];
    if (threadIdx.x < 17) s_acc[threadIdx.x] = 0.f;
    __syncthreads();
    float vals[17];
    vals[0] = r_nll;
#pragma unroll
    for (int c = 0; c < NC; c++) { vals[1+c]=r_cardp[c]; vals[9+c]=r_inter[c]; }
#pragma unroll
    for (int k = 0; k < 17; k++) {
        float v = vals[k];
#pragma unroll
        for (int o = 16; o; o >>= 1) v += __shfl_xor_sync(0xffffffffu, v, o);
        if ((threadIdx.x & 31) == 0) atomicAdd(&s_acc[k], v);
    }
    __syncthreads();
    int t = threadIdx.x;
    if (t == 0)       atomicAdd(&g_nll, s_acc[0]);
    else if (t < 9)   atomicAdd(&g_cardp[b][t-1], s_acc[t]);
    else if (t < 17)  atomicAdd(&g_inter[b][t-9], s_acc[t]);
}

// ------- pass A: segment sums as one-hot GEMM via mma.m16n8k16.bf16 ---------
// D[16ch][24seg] += E_chunk(16x16) @ OneHot(16x24), accumulators in registers.
__global__ void __launch_bounds__(256) segstat_kernel(const float* __restrict__ embed) {
    int b = blockIdx.y;
    const float* eb = embed + (size_t)b * NE * NVOX;
    const int*   pb = g_packed + (size_t)b * NVOX;

    int lane = threadIdx.x & 31;
    int warp = threadIdx.x >> 5;
    int gwarp = blockIdx.x * 8 + warp;
    int nwarps = gridDim.x * 8;

    int t  = lane & 3;       // threadID within group
    int gq = lane >> 2;      // group id 0..7

    float d[3][4];
#pragma unroll
    for (int f = 0; f < 3; f++)
#pragma unroll
        for (int r = 0; r < 4; r++) d[f][r] = 0.f;

    const float* r0base = eb + (size_t)gq * NVOX;
    const float* r1base = eb + (size_t)(gq + 8) * NVOX;

    for (int c = gwarp; c < NVOX/16; c += nwarps) {
        int base = c * 16;
        // labels for B: k = 2t,2t+1 and 2t+8,2t+9
        int2 pA = *(const int2*)(pb + base + 2*t);
        int2 pB = *(const int2*)(pb + base + 2*t + 8);
        // A tile: rows gq, gq+8; k pairs (2t,2t+1), (2t+8,2t+9)
        float2 a00 = *(const float2*)(r0base + base + 2*t);
        float2 a10 = *(const float2*)(r1base + base + 2*t);
        float2 a01 = *(const float2*)(r0base + base + 2*t + 8);
        float2 a11 = *(const float2*)(r1base + base + 2*t + 8);
        unsigned A0 = cvt_bf16x2(a00.x, a00.y);
        unsigned A1 = cvt_bf16x2(a10.x, a10.y);
        unsigned A2 = cvt_bf16x2(a01.x, a01.y);
        unsigned A3 = cvt_bf16x2(a11.x, a11.y);
#pragma unroll
        for (int f = 0; f < 3; f++) {
            int n = gq + 8*f;
            unsigned B0 = hb(pA.x, n) | (hb(pA.y, n) << 16);
            unsigned B1 = hb(pB.x, n) | (hb(pB.y, n) << 16);
            asm volatile(
                "mma.sync.aligned.m16n8k16.row.col.f32.bf16.bf16.f32 "
                "{%0,%1,%2,%3}, {%4,%5,%6,%7}, {%8,%9}, {%0,%1,%2,%3};"
                : "+f"(d[f][0]), "+f"(d[f][1]), "+f"(d[f][2]), "+f"(d[f][3])
                : "r"(A0), "r"(A1), "r"(A2), "r"(A3), "r"(B0), "r"(B1));
        }
    }

    // D layout: d[f][0]:(ch=gq,  seg=8f+2t)   d[f][1]:(ch=gq,  seg=8f+2t+1)
    //           d[f][2]:(ch=gq+8,seg=8f+2t)   d[f][3]:(ch=gq+8,seg=8f+2t+1)
    __shared__ float s_cnum[NSEG][NE];
    for (int j = threadIdx.x; j < NSEG*NE; j += blockDim.x) (&s_cnum[0][0])[j] = 0.f;
    __syncthreads();
#pragma unroll
    for (int f = 0; f < 3; f++) {
        int n0 = 8*f + 2*t;
        if (n0 < NSEG) {
            atomicAdd(&s_cnum[n0][gq],     d[f][0]);
            atomicAdd(&s_cnum[n0][gq + 8], d[f][2]);
        }
        if (n0 + 1 < NSEG) {
            atomicAdd(&s_cnum[n0+1][gq],     d[f][1]);
            atomicAdd(&s_cnum[n0+1][gq + 8], d[f][3]);
        }
    }
    __syncthreads();
    for (int j = threadIdx.x; j < NSEG*NE; j += blockDim.x) {
        float v = (&s_cnum[0][0])[j];
        if (v != 0.f) atomicAdd(&g_cnum[b][0][0] + j, v);
    }
}

// ---------------- centers + push + norm (tiny) ----------------
__global__ void centers_kernel() {
    int b = blockIdx.x;
    __shared__ float sc[NSEG][NE + 1];
    __shared__ int   s_present[NSEG];
    __shared__ float s_push, s_norm;
    __shared__ int   s_np;
    int tid = threadIdx.x;
    if (tid == 0) { s_push = 0.f; s_norm = 0.f; s_np = 0; }
    for (int j = tid; j < NSEG*NE; j += blockDim.x) {
        int k = j / NE, c = j % NE;
        float wsum = g_cnt[b][k] + 9.0f * g_bcnt[b][k];
        float cen = g_cnum[b][k][c] / (wsum + 1e-8f);
        g_centers[b][k][c] = cen;
        sc[k][c] = cen;
    }
    for (int k = tid; k < NSEG; k += blockDim.x) s_present[k] = (g_cnt[b][k] > 0.f) ? 1 : 0;
    __syncthreads();
    if (tid == 0) {
        int np = 0;
        for (int k = 1; k < NSEG; k++) np += s_present[k];
        s_np = np;
    }
    float pacc = 0.f;
    for (int p = tid; p < 120; p += blockDim.x) {
        int i = 1, rem = p;
        while (rem >= (NSEG - 1) - i) { rem -= (NSEG - 1) - i; i++; }
        int jj = i + 1 + rem;
        float ds = 0.f;
#pragma unroll
        for (int c = 0; c < NE; c++) { float dv = sc[i][c] - sc[jj][c]; ds += dv * dv; }
        float pw = sqrtf(ds);
        float tt = fmaxf(3.0f - pw, 0.f);
        if (s_present[i] && s_present[jj]) pacc += tt * tt;
    }
    atomicAdd(&s_push, pacc);
    float nacc = 0.f;
    for (int k = 1 + tid; k < NSEG; k += blockDim.x) {
        if (s_present[k]) {
            float ds = 0.f;
#pragma unroll
            for (int c = 0; c < NE; c++) ds += sc[k][c] * sc[k][c];
            nacc += sqrtf(ds);
        }
    }
    atomicAdd(&s_norm, nacc);
    __syncthreads();
    if (tid == 0) {
        float np = (float)s_np;
        float npairs = np * (np - 1.f) * 0.5f;
        g_push[b]  = (npairs > 0.f) ? s_push / fmaxf(npairs, 1.f) : 0.f;
        g_normv[b] = (np > 0.f)     ? s_norm / fmaxf(np, 1.f)     : 0.f;
        g_val[b]   = (np > 0.f) ? 1.f : 0.f;
    }
}

// ---------------- pass B: pull (vectorized) ----------------
__global__ void __launch_bounds__(256, 3) pull_kernel(const float* __restrict__ embed) {
    int b = blockIdx.y;
    __shared__ float sc[NSEG][NE + 1];
    __shared__ float s_pull[NSEG];
    for (int j = threadIdx.x; j < NSEG*NE; j += blockDim.x)
        sc[j / NE][j % NE] = g_centers[b][j / NE][j % NE];
    for (int j = threadIdx.x; j < NSEG; j += blockDim.x) s_pull[j] = 0.f;
    __syncthreads();

    const float4* eb = (const float4*)(embed + (size_t)b * NE * NVOX);
    const int4*   pb = (const int4*)(g_packed + (size_t)b * NVOX);

    int stride = gridDim.x * blockDim.x;
    for (int i = blockIdx.x * blockDim.x + threadIdx.x; i < NVOX/4; i += stride) {
        int4 p4 = pb[i];
        int   lv[4]; float wv[4]; float ds[4];
#pragma unroll
        for (int j = 0; j < 4; j++) {
            int p = (j==0) ? p4.x : (j==1) ? p4.y : (j==2) ? p4.z : p4.w;
            lv[j] = p & 0x7fffffff;
            wv[j] = (p < 0) ? 10.f : 1.f;
            ds[j] = 0.f;
        }
#pragma unroll
        for (int half = 0; half < 2; half++) {
            float4 e4[8];
#pragma unroll
            for (int c = 0; c < 8; c++)
                e4[c] = eb[(size_t)(half*8 + c) * (NVOX/4) + i];
#pragma unroll
            for (int c = 0; c < 8; c++) {
                int cc = half*8 + c;
#pragma unroll
                for (int j = 0; j < 4; j++) {
                    float ev = (j==0) ? e4[c].x : (j==1) ? e4[c].y : (j==2) ? e4[c].z : e4[c].w;
                    float dv = ev - sc[lv[j]][cc];
                    ds[j] += dv * dv;
                }
            }
        }
#pragma unroll
        for (int j = 0; j < 4; j++) {
            float dist = sqrtf(ds[j]);
            float tt = fmaxf(dist - 0.5f, 0.f);
            atomicAdd(&s_pull[lv[j]], tt * tt * wv[j]);
        }
    }
    __syncthreads();
    for (int j = threadIdx.x; j < NSEG; j += blockDim.x)
        atomicAdd(&g_pull[b][j], s_pull[j]);
}

// ---------------- final combine ----------------
__global__ void final_kernel(float* __restrict__ out) {
    if (threadIdx.x != 0 || blockIdx.x != 0) return;
    float Nf = (float)NTOT;
    float ce = g_nll / Nf;

    float dsum = 0.f;
    for (int b = 0; b < BATCH; b++)
        for (int c = 0; c < NC; c++)
            dsum += (2.0f * g_inter[b][c] + 1e-5f) /
                    (g_cardp[b][c] + g_hist[b][c] + 1e-5f);
    float dice = 1.0f - dsum / (float)(BATCH * NC);

    float lp = 0.f;
    for (int b = 0; b < BATCH; b++)
        for (int k = 1; k < NSEG; k++)
            if (g_cnt[b][k] > 0.f)
                lp += g_pull[b][k] / fmaxf(g_cnt[b][k], 1.f);

    float push = 0.f, nrm = 0.f, val = 0.f;
    for (int b = 0; b < BATCH; b++) { push += g_push[b]; nrm += g_normv[b]; val += g_val[b]; }

    float ins = (1.0f * lp + 1.0f * push + 0.001f * nrm) / fmaxf(val, 1.f);
    float sem = ce + dice;
    out[0] = sem + ins;
    out[1] = sem;
    out[2] = ce;
    out[3] = dice;
    out[4] = ins;
}

// ---------------- launch ----------------
extern "C" void kernel_launch(void* const* d_in, const int* in_sizes, int n_in,
                              void* d_out, int out_size) {
    const float* sem = (const float*)d_in[0];
    const float* emb = (const float*)d_in[1];
    const int*   cls = (const int*)d_in[2];
    const int*   lab = (const int*)d_in[3];
    float* out = (float*)d_out;

    zero_kernel<<<3, 256>>>();

    prep_kernel<<<NTOT / 256, 256>>>(lab, cls);

    dim3 g1(296, BATCH);
    ce_dice_kernel<<<g1, 256>>>(sem, cls);

    dim3 g2(296, BATCH);
    segstat_kernel<<<g2, 256>>>(emb);

    centers_kernel<<<BATCH, 128>>>();

    dim3 g3(296, BATCH);
    pull_kernel<<<g3, 256>>>(emb);

    final_kernel<<<1, 32>>>(out);
}